// round 1
// baseline (speedup 1.0000x reference)
#include <cuda_runtime.h>

#define SEQ     2048
#define NH      16
#define NB      4
#define DMODEL  1024
#define HD      64
#define KDIM    1024

// Scratch (device-global; allocation-free per harness rules)
__device__ float g_qkv[3][(size_t)NB * NH * SEQ * HD];   // [which][(b*NH+h)*SEQ + s][d]
__device__ float g_attn[(size_t)NB * SEQ * DMODEL];      // [b*SEQ + s][h*HD + d]

// ---------------------------------------------------------------------------
// 128x128x8 fp32 GEMM, 256 threads, 8x8 per-thread microtile (4+4 col chunks).
// A: [M,1024] row-major.  Bm: [1024,N] row-major.
// MODE 0: plain C = A*B into Cout [M,N]
// MODE 1: QKV projection — scatter epilogue into g_qkv head-major layout (N=3072)
// MODE 2: out projection — A is g_attn (param ignored), write Cout
// ---------------------------------------------------------------------------
template<int MODE>
__global__ __launch_bounds__(256) void gemm128(const float* __restrict__ A,
                                               const float* __restrict__ Bm,
                                               float* __restrict__ Cout, int N)
{
    __shared__ float As[8][128];   // transposed A tile: As[k][m]
    __shared__ float Bs[8][128];   // Bs[k][n]

    const float* Abase = (MODE == 2) ? (const float*)g_attn : A;

    const int tid = threadIdx.x;
    const int tx  = tid & 15, ty = tid >> 4;
    const int m0  = blockIdx.y * 128, n0 = blockIdx.x * 128;

    float acc[8][8];
#pragma unroll
    for (int i = 0; i < 8; i++)
#pragma unroll
        for (int j = 0; j < 8; j++) acc[i][j] = 0.f;

    const int arow = tid >> 1, acol = (tid & 1) << 2;   // A tile 128x8
    const int brow = tid >> 5, bcol = (tid & 31) << 2;  // B tile 8x128
    const float* Ap = Abase + (size_t)(m0 + arow) * KDIM + acol;
    const float* Bp = Bm + (size_t)brow * N + n0 + bcol;

    for (int k0 = 0; k0 < KDIM; k0 += 8) {
        float4 av = *(const float4*)(Ap + k0);
        float4 bv = *(const float4*)(Bp + (size_t)k0 * N);
        __syncthreads();
        As[acol + 0][arow] = av.x;
        As[acol + 1][arow] = av.y;
        As[acol + 2][arow] = av.z;
        As[acol + 3][arow] = av.w;
        *(float4*)&Bs[brow][bcol] = bv;
        __syncthreads();
#pragma unroll
        for (int kk = 0; kk < 8; kk++) {
            float ra[8], rb[8];
            *(float4*)(ra)     = *(const float4*)&As[kk][ty * 4];
            *(float4*)(ra + 4) = *(const float4*)&As[kk][64 + ty * 4];
            *(float4*)(rb)     = *(const float4*)&Bs[kk][tx * 4];
            *(float4*)(rb + 4) = *(const float4*)&Bs[kk][64 + tx * 4];
#pragma unroll
            for (int i = 0; i < 8; i++)
#pragma unroll
                for (int j = 0; j < 8; j++)
                    acc[i][j] = fmaf(ra[i], rb[j], acc[i][j]);
        }
    }

    if (MODE == 1) {
        // Scatter into g_qkv: col n -> which = n/1024, head = (n%1024)/64, d = n%64
        const int b_ = m0 >> 11;                 // 2048 % 128 == 0 -> constant per block
        const int nA = n0 + tx * 4, nB = nA + 64;
        const int wA = nA >> 10, hA = (nA >> 6) & (NH - 1);
        const int wB = nB >> 10, hB = (nB >> 6) & (NH - 1);
        const int dc = tx * 4;                   // n0 % 64 == 0
#pragma unroll
        for (int i = 0; i < 8; i++) {
            int m = m0 + ((i < 4) ? (ty * 4 + i) : (64 + ty * 4 + i - 4));
            int s = m & (SEQ - 1);
            float4 v0 = make_float4(acc[i][0], acc[i][1], acc[i][2], acc[i][3]);
            float4 v1 = make_float4(acc[i][4], acc[i][5], acc[i][6], acc[i][7]);
            *(float4*)&g_qkv[wA][(((size_t)b_ * NH + hA) * SEQ + s) * HD + dc] = v0;
            *(float4*)&g_qkv[wB][(((size_t)b_ * NH + hB) * SEQ + s) * HD + dc] = v1;
        }
    } else {
#pragma unroll
        for (int i = 0; i < 8; i++) {
            int m = m0 + ((i < 4) ? (ty * 4 + i) : (64 + ty * 4 + i - 4));
            float4 v0 = make_float4(acc[i][0], acc[i][1], acc[i][2], acc[i][3]);
            float4 v1 = make_float4(acc[i][4], acc[i][5], acc[i][6], acc[i][7]);
            *(float4*)(Cout + (size_t)m * N + n0 + tx * 4)      = v0;
            *(float4*)(Cout + (size_t)m * N + n0 + 64 + tx * 4) = v1;
        }
    }
}

// ---------------------------------------------------------------------------
// Flash attention, fp32. One CTA = one (b,h) x one 64-row q-tile.
// 256 threads; thread (tx,ty) owns a 4x4 microtile of S[64,64] and of O[64,64].
// Q,K stored transposed [d][s] in smem with XOR-4 swizzle -> conflict-free LDS.128.
// ---------------------------------------------------------------------------
__global__ __launch_bounds__(256) void attn_kernel()
{
    extern __shared__ float smbuf[];
    float* Qt = smbuf;            // 4096 floats: Qt[d*64 + (q ^ swz(d))]
    float* Kt = smbuf + 4096;     // 4096 floats: Kt[d*64 + (k ^ swz(d))]
    float* Vs = smbuf + 8192;     // 4096 floats: Vs[k*64 + d]
    float* Ps = smbuf + 12288;    // 4096 floats: Ps[q*64 + k]

    const int qt  = (int)(gridDim.x - 1 - blockIdx.x);  // heavy tiles first
    const int bh  = blockIdx.y;
    const int tid = threadIdx.x, tx = tid & 15, ty = tid >> 4;

    const float* Qg = g_qkv[0] + ((size_t)bh * SEQ + qt * 64) * HD;
    const float* Kg = g_qkv[1] + (size_t)bh * SEQ * HD;
    const float* Vg = g_qkv[2] + (size_t)bh * SEQ * HD;

    // Load Q tile transposed + swizzled
    for (int idx = tid; idx < 1024; idx += 256) {
        int s = idx >> 4, c4 = (idx & 15) << 2;
        float4 f = *(const float4*)(Qg + s * HD + c4);
        int p = (c4 << 6) + (s ^ ((idx & 7) << 2));
        Qt[p] = f.x; Qt[p + 64] = f.y; Qt[p + 128] = f.z; Qt[p + 192] = f.w;
    }

    float m_i[4], l_i[4], o[4][4];
#pragma unroll
    for (int i = 0; i < 4; i++) {
        m_i[i] = -1e30f; l_i[i] = 0.f;
#pragma unroll
        for (int j = 0; j < 4; j++) o[i][j] = 0.f;
    }

    for (int kt = 0; kt <= qt; kt++) {
        const float* kg = Kg + (size_t)kt * 64 * HD;
        const float* vg = Vg + (size_t)kt * 64 * HD;
        for (int idx = tid; idx < 1024; idx += 256) {
            int s = idx >> 4, c4 = (idx & 15) << 2;
            float4 f = *(const float4*)(kg + s * HD + c4);
            int p = (c4 << 6) + (s ^ ((idx & 7) << 2));
            Kt[p] = f.x; Kt[p + 64] = f.y; Kt[p + 128] = f.z; Kt[p + 192] = f.w;
            float4 g = *(const float4*)(vg + s * HD + c4);
            *(float4*)(Vs + (s << 6) + c4) = g;
        }
        __syncthreads();   // covers Q load on first iter, KV reuse afterwards

        // S = Q K^T  (64x64, per-thread 4x4)
        float sacc[4][4];
#pragma unroll
        for (int i = 0; i < 4; i++)
#pragma unroll
            for (int j = 0; j < 4; j++) sacc[i][j] = 0.f;

#pragma unroll 8
        for (int d = 0; d < 64; d++) {
            int swz = ((d >> 2) & 7) << 2;
            float4 qv = *(const float4*)(Qt + (d << 6) + ((ty * 4) ^ swz));
            float4 kv = *(const float4*)(Kt + (d << 6) + ((tx * 4) ^ swz));
            float qa[4] = {qv.x, qv.y, qv.z, qv.w};
            float ka[4] = {kv.x, kv.y, kv.z, kv.w};
#pragma unroll
            for (int i = 0; i < 4; i++)
#pragma unroll
                for (int j = 0; j < 4; j++)
                    sacc[i][j] = fmaf(qa[i], ka[j], sacc[i][j]);
        }

        // scale + causal mask + online softmax (row reduce across 16 lanes)
        const bool diag = (kt == qt);
#pragma unroll
        for (int i = 0; i < 4; i++) {
            float mx = -1e30f;
#pragma unroll
            for (int j = 0; j < 4; j++) {
                float v = sacc[i][j] * 0.125f;           // 1/sqrt(64)
                if (diag && (tx * 4 + j) > (ty * 4 + i)) v = -1e30f;
                sacc[i][j] = v;
                mx = fmaxf(mx, v);
            }
#pragma unroll
            for (int sh = 8; sh >= 1; sh >>= 1)
                mx = fmaxf(mx, __shfl_xor_sync(0xffffffffu, mx, sh, 32));
            float mnew  = fmaxf(m_i[i], mx);
            float alpha = __expf(m_i[i] - mnew);
            m_i[i] = mnew;
            float rs = 0.f;
#pragma unroll
            for (int j = 0; j < 4; j++) {
                float p = __expf(sacc[i][j] - mnew);
                sacc[i][j] = p;
                rs += p;
            }
#pragma unroll
            for (int sh = 8; sh >= 1; sh >>= 1)
                rs += __shfl_xor_sync(0xffffffffu, rs, sh, 32);
            l_i[i] = l_i[i] * alpha + rs;
#pragma unroll
            for (int j = 0; j < 4; j++) o[i][j] *= alpha;
        }

        // P -> smem
#pragma unroll
        for (int i = 0; i < 4; i++)
            *(float4*)(Ps + ((ty * 4 + i) << 6) + tx * 4) =
                make_float4(sacc[i][0], sacc[i][1], sacc[i][2], sacc[i][3]);
        __syncthreads();

        // O += P @ V
#pragma unroll 8
        for (int kk = 0; kk < 64; kk++) {
            float4 vv = *(const float4*)(Vs + (kk << 6) + tx * 4);
            float va[4] = {vv.x, vv.y, vv.z, vv.w};
            float pr[4];
#pragma unroll
            for (int i = 0; i < 4; i++) pr[i] = Ps[((ty * 4 + i) << 6) + kk];
#pragma unroll
            for (int i = 0; i < 4; i++)
#pragma unroll
                for (int j = 0; j < 4; j++)
                    o[i][j] = fmaf(pr[i], va[j], o[i][j]);
        }
        __syncthreads();   // guard Kt/Vs/Ps overwrite next iteration
    }

    // epilogue: normalize and store into [b, s, h*64+d] layout for out-proj GEMM
    const int b_ = bh >> 4, h = bh & (NH - 1);
#pragma unroll
    for (int i = 0; i < 4; i++) {
        float inv = 1.0f / l_i[i];
        int srow = qt * 64 + ty * 4 + i;
        float4 v = make_float4(o[i][0] * inv, o[i][1] * inv, o[i][2] * inv, o[i][3] * inv);
        *(float4*)(g_attn + ((size_t)b_ * SEQ + srow) * DMODEL + h * HD + tx * 4) = v;
    }
}

// ---------------------------------------------------------------------------

extern "C" void kernel_launch(void* const* d_in, const int* in_sizes, int n_in,
                              void* d_out, int out_size)
{
    const float* x      = (const float*)d_in[0];   // [4,2048,1024]
    const float* w_qkv  = (const float*)d_in[1];   // [1024,3072]
    const float* w_out  = (const float*)d_in[2];   // [1024,1024]
    float* out = (float*)d_out;                    // [4,2048,1024]

    // 1) QKV projection with head-major scatter epilogue
    gemm128<1><<<dim3((3 * DMODEL) / 128, (NB * SEQ) / 128), 256>>>(x, w_qkv, nullptr, 3 * DMODEL);

    // 2) causal flash attention
    cudaFuncSetAttribute(attn_kernel, cudaFuncAttributeMaxDynamicSharedMemorySize, 65536);
    attn_kernel<<<dim3(SEQ / 64, NB * NH), 256, 65536>>>();

    // 3) output projection
    gemm128<2><<<dim3(DMODEL / 128, (NB * SEQ) / 128), 256>>>(nullptr, w_out, out, DMODEL);
}

// round 7
// speedup vs baseline: 2.3246x; 2.3246x over previous
#include <cuda_runtime.h>

#define SEQ     2048
#define NH      16
#define NB      4
#define DMODEL  1024
#define HD      64
#define KDIM    1024

// Scratch (device-global; allocation-free per harness rules)
__device__ float g_qkv[3][(size_t)NB * NH * SEQ * HD];   // [which][(b*NH+h)*SEQ + s][d]
__device__ float g_attn[(size_t)NB * SEQ * DMODEL];      // [b*SEQ + s][h*HD + d]

__device__ __forceinline__ unsigned f2tf(float f) {
    unsigned u;
    asm("cvt.rna.tf32.f32 %0, %1;" : "=r"(u) : "f"(f));
    return u;
}

__device__ __forceinline__ void mma_tf32(float c[4], unsigned a0, unsigned a1,
                                         unsigned a2, unsigned a3,
                                         unsigned b0, unsigned b1) {
    asm volatile(
        "mma.sync.aligned.m16n8k8.row.col.f32.tf32.tf32.f32 "
        "{%0,%1,%2,%3}, {%4,%5,%6,%7}, {%8,%9}, {%0,%1,%2,%3};"
        : "+f"(c[0]), "+f"(c[1]), "+f"(c[2]), "+f"(c[3])
        : "r"(a0), "r"(a1), "r"(a2), "r"(a3), "r"(b0), "r"(b1));
}

// ---------------------------------------------------------------------------
// TF32 tensor-core GEMM. CTA tile 128x128, k-stage 32, 8 warps (4m x 2n),
// warp tile 32x64 via m16n8k8. A:[M,1024] rm, B:[1024,N] rm.
// MODE 1: QKV projection, scatter into g_qkv. MODE 2: A = g_attn. MODE 0: plain.
// ---------------------------------------------------------------------------
template<int MODE>
__global__ __launch_bounds__(256) void gemm_tc(const float* __restrict__ A,
                                               const float* __restrict__ Bm,
                                               float* __restrict__ Cout, int N)
{
    __shared__ unsigned As[128][36];   // As[m][k], pad 36 -> conflict-free a-frags
    __shared__ unsigned Bs[32][136];   // Bs[k][n], pad 136 -> conflict-free b-frags

    const float* Abase = (MODE == 2) ? (const float*)g_attn : A;

    const int tid    = threadIdx.x;
    const int warp   = tid >> 5;
    const int lane   = tid & 31;
    const int g      = lane >> 2;      // group id 0..7
    const int t      = lane & 3;       // thread-in-group 0..3
    const int warp_m = (warp & 3) * 32;
    const int warp_n = (warp >> 2) * 64;
    const int m0     = blockIdx.y * 128;
    const int n0     = blockIdx.x * 128;

    float acc[2][8][4];
#pragma unroll
    for (int mi = 0; mi < 2; mi++)
#pragma unroll
        for (int ni = 0; ni < 8; ni++)
#pragma unroll
            for (int j = 0; j < 4; j++) acc[mi][ni][j] = 0.f;

    const int arow  = tid >> 1;              // 0..127
    const int akoff = (tid & 1) * 16;
    const int bcol  = (tid & 31) * 4;
    const int brow0 = tid >> 5;              // 0..7

    const float* Ap = Abase + (size_t)(m0 + arow) * KDIM + akoff;
    const float* Bp = Bm + n0 + bcol;

    for (int K0 = 0; K0 < KDIM; K0 += 32) {
        // load + cvt + stage
#pragma unroll
        for (int i = 0; i < 4; i++) {
            float4 v = *(const float4*)(Ap + K0 + i * 4);
            uint4 u = make_uint4(f2tf(v.x), f2tf(v.y), f2tf(v.z), f2tf(v.w));
            *(uint4*)&As[arow][akoff + i * 4] = u;
        }
#pragma unroll
        for (int i = 0; i < 4; i++) {
            int kr = brow0 + i * 8;
            float4 v = *(const float4*)(Bp + (size_t)(K0 + kr) * N);
            uint4 u = make_uint4(f2tf(v.x), f2tf(v.y), f2tf(v.z), f2tf(v.w));
            *(uint4*)&Bs[kr][bcol] = u;
        }
        __syncthreads();

#pragma unroll
        for (int kk = 0; kk < 32; kk += 8) {
            unsigned a[2][4], b[8][2];
#pragma unroll
            for (int mi = 0; mi < 2; mi++) {
                int r0 = warp_m + mi * 16 + g;
                a[mi][0] = As[r0][kk + t];
                a[mi][1] = As[r0 + 8][kk + t];
                a[mi][2] = As[r0][kk + t + 4];
                a[mi][3] = As[r0 + 8][kk + t + 4];
            }
#pragma unroll
            for (int ni = 0; ni < 8; ni++) {
                int n = warp_n + ni * 8 + g;
                b[ni][0] = Bs[kk + t][n];
                b[ni][1] = Bs[kk + t + 4][n];
            }
#pragma unroll
            for (int mi = 0; mi < 2; mi++)
#pragma unroll
                for (int ni = 0; ni < 8; ni++)
                    mma_tf32(acc[mi][ni], a[mi][0], a[mi][1], a[mi][2], a[mi][3],
                             b[ni][0], b[ni][1]);
        }
        __syncthreads();
    }

    if (MODE == 1) {
        // scatter into g_qkv: global col -> which = n/1024, head = (n%1024)/64, d = n%64
        const int b_ = m0 >> 11;
        const int nbase = n0 + warp_n;           // 64-aligned, never straddles a head
        const int which = nbase >> 10;
        const int head  = (nbase >> 6) & (NH - 1);
        float* base = g_qkv[which] + (((size_t)b_ * NH + head) * SEQ) * HD;
#pragma unroll
        for (int mi = 0; mi < 2; mi++) {
            int s0 = (m0 + warp_m + mi * 16 + g) & (SEQ - 1);
#pragma unroll
            for (int ni = 0; ni < 8; ni++) {
                int d = ni * 8 + 2 * t;
                *(float2*)(base + (size_t)s0 * HD + d) =
                    make_float2(acc[mi][ni][0], acc[mi][ni][1]);
                *(float2*)(base + (size_t)(s0 + 8) * HD + d) =
                    make_float2(acc[mi][ni][2], acc[mi][ni][3]);
            }
        }
    } else {
#pragma unroll
        for (int mi = 0; mi < 2; mi++) {
            int r = m0 + warp_m + mi * 16 + g;
#pragma unroll
            for (int ni = 0; ni < 8; ni++) {
                int n = n0 + warp_n + ni * 8 + 2 * t;
                *(float2*)(Cout + (size_t)r * N + n) =
                    make_float2(acc[mi][ni][0], acc[mi][ni][1]);
                *(float2*)(Cout + (size_t)(r + 8) * N + n) =
                    make_float2(acc[mi][ni][2], acc[mi][ni][3]);
            }
        }
    }
}

// ---------------------------------------------------------------------------
// TF32 tensor-core causal flash attention.
// CTA = 128 threads (4 warps) x one 64-row q-tile of one (b,h).
// Warp = 16 q-rows x full 64 k-width -> softmax row-reduce stays in-warp.
// Q lives in registers as pre-built a-fragments for the whole kernel.
// ---------------------------------------------------------------------------
__global__ __launch_bounds__(128) void attn_tc()
{
    extern __shared__ unsigned smu[];
    unsigned* Ks = smu;                 // [64][68] tf32, conflict-free S b-frags
    unsigned* Vs = smu + 64 * 68;       // [64][72] tf32, conflict-free PV b-frags
    unsigned* Ps = smu + 64 * 68 + 64 * 72;  // 4 warps x [16][68]

    const int qt   = (int)(gridDim.x - 1 - blockIdx.x);  // heavy tiles first
    const int bh   = blockIdx.y;
    const int tid  = threadIdx.x;
    const int warp = tid >> 5;
    const int lane = tid & 31;
    const int g    = lane >> 2;
    const int t    = lane & 3;

    const float* Qg = g_qkv[0] + ((size_t)bh * SEQ + qt * 64) * HD;
    const float* Kg = g_qkv[1] + (size_t)bh * SEQ * HD;
    const float* Vg = g_qkv[2] + (size_t)bh * SEQ * HD;

    // Q a-fragments in registers (scaled by 1/sqrt(64) here once)
    unsigned qa[8][4];
    {
        const float* q0 = Qg + (warp * 16 + g) * HD;
        const float* q1 = q0 + 8 * HD;
#pragma unroll
        for (int kk8 = 0; kk8 < 8; kk8++) {
            int c = kk8 * 8 + t;
            qa[kk8][0] = f2tf(q0[c] * 0.125f);
            qa[kk8][1] = f2tf(q1[c] * 0.125f);
            qa[kk8][2] = f2tf(q0[c + 4] * 0.125f);
            qa[kk8][3] = f2tf(q1[c + 4] * 0.125f);
        }
    }

    float m_i[2] = {-1e30f, -1e30f};
    float l_i[2] = {0.f, 0.f};
    float o[8][4];
#pragma unroll
    for (int ni = 0; ni < 8; ni++)
#pragma unroll
        for (int j = 0; j < 4; j++) o[ni][j] = 0.f;

    const int qrow0 = qt * 64 + warp * 16 + g;   // this thread's row (half 0)
    unsigned* Pw = Ps + warp * 16 * 68;

    const int ldrow  = tid >> 1;               // 0..63
    const int ldcoff = (tid & 1) * 32;

    for (int kt = 0; kt <= qt; kt++) {
        __syncthreads();   // prior iteration finished reading Ks/Vs
        {
            const float* kg = Kg + (size_t)kt * 64 * HD + ldrow * HD + ldcoff;
            const float* vg = Vg + (size_t)kt * 64 * HD + ldrow * HD + ldcoff;
#pragma unroll
            for (int i = 0; i < 8; i++) {
                float4 kv = *(const float4*)(kg + i * 4);
                *(uint4*)&Ks[ldrow * 68 + ldcoff + i * 4] =
                    make_uint4(f2tf(kv.x), f2tf(kv.y), f2tf(kv.z), f2tf(kv.w));
                float4 vv = *(const float4*)(vg + i * 4);
                *(uint4*)&Vs[ldrow * 72 + ldcoff + i * 4] =
                    make_uint4(f2tf(vv.x), f2tf(vv.y), f2tf(vv.z), f2tf(vv.w));
            }
        }
        __syncthreads();

        // S = (Q/8) K^T : warp computes 16 x 64
        float s[8][4];
#pragma unroll
        for (int ni = 0; ni < 8; ni++)
#pragma unroll
            for (int j = 0; j < 4; j++) s[ni][j] = 0.f;

#pragma unroll
        for (int kk8 = 0; kk8 < 8; kk8++) {
            int c = kk8 * 8 + t;
            unsigned b[8][2];
#pragma unroll
            for (int ni = 0; ni < 8; ni++) {
                int ks = ni * 8 + g;
                b[ni][0] = Ks[ks * 68 + c];
                b[ni][1] = Ks[ks * 68 + c + 4];
            }
#pragma unroll
            for (int ni = 0; ni < 8; ni++)
                mma_tf32(s[ni], qa[kk8][0], qa[kk8][1], qa[kk8][2], qa[kk8][3],
                         b[ni][0], b[ni][1]);
        }

        // causal mask (only the diagonal tile needs it)
        if (kt == qt) {
            int colb = kt * 64 + 2 * t;
#pragma unroll
            for (int ni = 0; ni < 8; ni++) {
                int c0 = colb + ni * 8;
                if (c0 > qrow0)     s[ni][0] = -1e30f;
                if (c0 + 1 > qrow0) s[ni][1] = -1e30f;
                if (c0 > qrow0 + 8)     s[ni][2] = -1e30f;
                if (c0 + 1 > qrow0 + 8) s[ni][3] = -1e30f;
            }
        }

        // online softmax per row-half (rows lane/4 and lane/4+8) — in-warp
#pragma unroll
        for (int h = 0; h < 2; h++) {
            float mx = -1e30f;
#pragma unroll
            for (int ni = 0; ni < 8; ni++) {
                mx = fmaxf(mx, s[ni][h * 2]);
                mx = fmaxf(mx, s[ni][h * 2 + 1]);
            }
            mx = fmaxf(mx, __shfl_xor_sync(0xffffffffu, mx, 1, 32));
            mx = fmaxf(mx, __shfl_xor_sync(0xffffffffu, mx, 2, 32));
            float mnew  = fmaxf(m_i[h], mx);
            float alpha = __expf(m_i[h] - mnew);
            m_i[h] = mnew;
            float rs = 0.f;
#pragma unroll
            for (int ni = 0; ni < 8; ni++) {
                float p0 = __expf(s[ni][h * 2] - mnew);
                float p1 = __expf(s[ni][h * 2 + 1] - mnew);
                s[ni][h * 2] = p0;
                s[ni][h * 2 + 1] = p1;
                rs += p0 + p1;
            }
            rs += __shfl_xor_sync(0xffffffffu, rs, 1, 32);
            rs += __shfl_xor_sync(0xffffffffu, rs, 2, 32);
            l_i[h] = l_i[h] * alpha + rs;
#pragma unroll
            for (int ni = 0; ni < 8; ni++) {
                o[ni][h * 2] *= alpha;
                o[ni][h * 2 + 1] *= alpha;
            }
        }

        // P -> warp-private smem (c-frag layout -> a-frag layout)
#pragma unroll
        for (int ni = 0; ni < 8; ni++) {
            int c = ni * 8 + 2 * t;
            Pw[g * 68 + c]           = f2tf(s[ni][0]);
            Pw[g * 68 + c + 1]       = f2tf(s[ni][1]);
            Pw[(g + 8) * 68 + c]     = f2tf(s[ni][2]);
            Pw[(g + 8) * 68 + c + 1] = f2tf(s[ni][3]);
        }
        __syncwarp();

        // O += P @ V
#pragma unroll
        for (int kk8 = 0; kk8 < 8; kk8++) {
            int c = kk8 * 8 + t;
            unsigned pa0 = Pw[g * 68 + c];
            unsigned pa1 = Pw[(g + 8) * 68 + c];
            unsigned pa2 = Pw[g * 68 + c + 4];
            unsigned pa3 = Pw[(g + 8) * 68 + c + 4];
#pragma unroll
            for (int ni = 0; ni < 8; ni++) {
                int d = ni * 8 + g;
                unsigned b0 = Vs[c * 72 + d];
                unsigned b1 = Vs[(c + 4) * 72 + d];
                mma_tf32(o[ni], pa0, pa1, pa2, pa3, b0, b1);
            }
        }
        __syncwarp();   // Pw reads done before next iteration overwrites
    }

    // epilogue: normalize, write [b, s, h*64+d] for the out-projection
    const int b_ = bh >> 4, h_ = bh & (NH - 1);
    float inv0 = 1.0f / l_i[0], inv1 = 1.0f / l_i[1];
    float* ob = g_attn + ((size_t)b_ * SEQ + qrow0) * DMODEL + h_ * HD;
#pragma unroll
    for (int ni = 0; ni < 8; ni++) {
        int d = ni * 8 + 2 * t;
        *(float2*)(ob + d) = make_float2(o[ni][0] * inv0, o[ni][1] * inv0);
        *(float2*)(ob + (size_t)8 * DMODEL + d) =
            make_float2(o[ni][2] * inv1, o[ni][3] * inv1);
    }
}

// ---------------------------------------------------------------------------

extern "C" void kernel_launch(void* const* d_in, const int* in_sizes, int n_in,
                              void* d_out, int out_size)
{
    const float* x      = (const float*)d_in[0];   // [4,2048,1024]
    const float* w_qkv  = (const float*)d_in[1];   // [1024,3072]
    const float* w_out  = (const float*)d_in[2];   // [1024,1024]
    float* out = (float*)d_out;                    // [4,2048,1024]

    // 1) QKV projection with head-major scatter epilogue
    gemm_tc<1><<<dim3((3 * DMODEL) / 128, (NB * SEQ) / 128), 256>>>(x, w_qkv, nullptr, 3 * DMODEL);

    // 2) causal flash attention (tf32 tensor cores)
    cudaFuncSetAttribute(attn_tc, cudaFuncAttributeMaxDynamicSharedMemorySize,
                         (64 * 68 + 64 * 72 + 4 * 16 * 68) * 4);
    attn_tc<<<dim3(SEQ / 64, NB * NH), 128, (64 * 68 + 64 * 72 + 4 * 16 * 68) * 4>>>();

    // 3) output projection
    gemm_tc<2><<<dim3(DMODEL / 128, (NB * SEQ) / 128), 256>>>(nullptr, w_out, out, DMODEL);
}